// round 14
// baseline (speedup 1.0000x reference)
#include <cuda_runtime.h>
#include <cuda_fp16.h>
#include <cstdint>
#include <math.h>

#define B_TOTAL 16384
#define F_DIM   512
#define P_DIM   128
#define C_DIM   10
#define MT      128
#define KC      128
#define NCHUNK  4
#define THREADS 512

// fp16 tile rows: 128 elems = 256B + 16B pad -> 272B stride (ldmatrix conflict-free)
#define RS_BY   272
#define TILE_BY (128 * RS_BY)            // 34816 B
#define STAGE_BY (2 * TILE_BY)           // 69632 B : A | B
#define A_BY    0
#define B_BY    TILE_BY

#define SARR_OFF    0
#define SARR_STRIDE 132                            // float4-aligned, conflict-free
#define U_OFF       (2 * STAGE_BY / 4)             // 34816 floats (after 2 stages)
#define UT_FLOATS   (P_DIM * 12)                   // 1536
#define XNORM_OFF   (U_OFF + UT_FLOATS)
#define WNORM_OFF   (XNORM_OFF + 128)
#define GAMMA_OFF   (WNORM_OFF + 128)
#define ALPHA_OFF   (GAMMA_OFF + 128)
#define XPART_OFF   (ALPHA_OFF + 128)
#define SMEM_FLOATS (XPART_OFF + 512)
#define SMEM_ALLOC  (SMEM_FLOATS * 4 + 1024)

// w chunk tile in gmem: 128 rows x 128 fp16 = 32768 B
#define WCH_BY 32768

__device__ __align__(256) __half g_wh[NCHUNK * P_DIM * KC];
__device__ float g_params[384 + UT_FLOATS];   // wnorm|gamma|alpha|uT(p-major,pad12)

__device__ __forceinline__ uint32_t smem_u32(const void* p) {
    uint32_t a;
    asm("{ .reg .u64 t; cvta.to.shared.u64 t, %1; cvt.u32.u64 %0, t; }"
        : "=r"(a) : "l"(p));
    return a;
}
__device__ __forceinline__ uint32_t pack_f16x2(float lo_elem, float hi_elem) {
    uint32_t r;
    asm("cvt.rn.f16x2.f32 %0, %1, %2;" : "=r"(r) : "f"(hi_elem), "f"(lo_elem));
    return r;
}
// ---- packed f32x2 helpers (sm_100+ base ISA) ----
__device__ __forceinline__ uint64_t pk2(float lo, float hi) {
    uint64_t d;
    asm("mov.b64 %0, {%1, %2};" : "=l"(d)
        : "r"(__float_as_uint(lo)), "r"(__float_as_uint(hi)));
    return d;
}
__device__ __forceinline__ void unpk2(uint64_t v, float& lo, float& hi) {
    uint32_t a, b;
    asm("mov.b64 {%0, %1}, %2;" : "=r"(a), "=r"(b) : "l"(v));
    lo = __uint_as_float(a); hi = __uint_as_float(b);
}
__device__ __forceinline__ uint64_t fma2(uint64_t a, uint64_t b, uint64_t c) {
    uint64_t d;
    asm("fma.rn.f32x2 %0, %1, %2, %3;" : "=l"(d) : "l"(a), "l"(b), "l"(c));
    return d;
}
__device__ __forceinline__ uint64_t mul2(uint64_t a, uint64_t b) {
    uint64_t d;
    asm("mul.rn.f32x2 %0, %1, %2;" : "=l"(d) : "l"(a), "l"(b));
    return d;
}
__device__ __forceinline__ uint64_t add2(uint64_t a, uint64_t b) {
    uint64_t d;
    asm("add.rn.f32x2 %0, %1, %2;" : "=l"(d) : "l"(a), "l"(b));
    return d;
}

#define LDSM4(r, addr) \
    asm volatile("ldmatrix.sync.aligned.m8n8.x4.shared.b16 {%0,%1,%2,%3}, [%4];" \
        : "=r"((r)[0]), "=r"((r)[1]), "=r"((r)[2]), "=r"((r)[3]) : "r"(addr))
#define MMA(acc, a, b0, b1) \
    asm volatile("mma.sync.aligned.m16n8k16.row.col.f32.f16.f16.f32 " \
        "{%0,%1,%2,%3}, {%4,%5,%6,%7}, {%8,%9}, {%0,%1,%2,%3};" \
        : "+f"((acc)[0]), "+f"((acc)[1]), "+f"((acc)[2]), "+f"((acc)[3]) \
        : "r"((a)[0]), "r"((a)[1]), "r"((a)[2]), "r"((a)[3]), "r"(b0), "r"(b1))
#define CPA16(dst, src) \
    asm volatile("cp.async.cg.shared.global [%0], [%1], 16;" :: "r"(dst), "l"(src) : "memory")
#define CP_COMMIT() asm volatile("cp.async.commit_group;" ::: "memory")
#define CP_WAIT0()  asm volatile("cp.async.wait_group 0;" ::: "memory")

// convert 8 fp32 (regs) -> 8 fp16 (RN) into dst (16B); returns fp32 sum of squares
__device__ __forceinline__ float conv8h(float4 v0, float4 v1, char* dst) {
    uint4 h;
    h.x = pack_f16x2(v0.x, v0.y);
    h.y = pack_f16x2(v0.z, v0.w);
    h.z = pack_f16x2(v1.x, v1.y);
    h.w = pack_f16x2(v1.z, v1.w);
    *(uint4*)dst = h;
    return v0.x*v0.x + v0.y*v0.y + v0.z*v0.z + v0.w*v0.w
         + v1.x*v1.x + v1.y*v1.y + v1.z*v1.z + v1.w*v1.w;
}

// ------------------------- prep kernel: w -> fp16 + params ------------------
__global__ __launch_bounds__(128)
void prep_kernel(const float* __restrict__ w,
                 const float* __restrict__ eta,
                 const float* __restrict__ xi,
                 const float* __restrict__ beta)
{
    __shared__ float sred[128];
    const int p = blockIdx.x;
    const int t = threadIdx.x;
    float4 v = ((const float4*)(w + (size_t)p * F_DIM))[t];
    uint32_t h0 = pack_f16x2(v.x, v.y);
    uint32_t h1 = pack_f16x2(v.z, v.w);
    const int c = t >> 5;            // chunk (4 chunks of 128 k = 32 float4)
    const int k = (t & 31) << 2;     // k within chunk
    const int idx = c * (P_DIM * KC) + p * KC + k;
    *(uint2*)&g_wh[idx] = make_uint2(h0, h1);

    sred[t] = v.x*v.x + v.y*v.y + v.z*v.z + v.w*v.w;
    __syncthreads();
    #pragma unroll
    for (int o = 64; o > 0; o >>= 1) {
        if (t < o) sred[t] += sred[t + o];
        __syncthreads();
    }
    if (t == 0) {
        g_params[p] = sred[0];
        float e = eta[p];
        g_params[128 + p] = e * e;
        g_params[256 + p] = 1.0f / (1.0f + expf(-xi[p]));
        float b2[C_DIM]; float bs = 0.f;
        #pragma unroll
        for (int cc = 0; cc < C_DIM; ++cc) {
            float bv = beta[cc * P_DIM + p];
            b2[cc] = bv * bv; bs += b2[cc];
        }
        float binv = 1.0f / bs;
        #pragma unroll
        for (int cc = 0; cc < C_DIM; ++cc)
            g_params[384 + p * 12 + cc] = b2[cc] * binv;
        g_params[384 + p * 12 + 10] = 0.f;
        g_params[384 + p * 12 + 11] = 0.f;
    }
}

// ------------------------------- main kernel --------------------------------
__global__ __launch_bounds__(THREADS, 1)
void ds_mma_kernel(const float* __restrict__ x,
                   float* __restrict__ out)
{
    extern __shared__ char dsm[];
    uintptr_t ga = ((uintptr_t)dsm + 1023) & ~(uintptr_t)1023;
    float* smf = (float*)ga;
    char*  smc = (char*)ga;
    const uint32_t sb = smem_u32(smf);

    const int tid  = threadIdx.x;
    const int lane = tid & 31;
    const int wid  = tid >> 5;
    const int wid_m = wid >> 2;
    const int wid_n = wid & 3;
    const int blockRow = blockIdx.x * MT;

    // params -> smem
    #pragma unroll
    for (int i = tid; i < 384; i += THREADS) smf[WNORM_OFF + i] = g_params[i];
    #pragma unroll
    for (int i = tid; i < UT_FLOATS; i += THREADS) smf[U_OFF + i] = g_params[384 + i];

    // x conversion mapping: one row-quarter (32 floats) per thread
    const int r0 = tid >> 2;            // 0..127
    const int kq = (tid & 3) << 5;      // 0,32,64,96 (floats)
    const float* xrow = x + (size_t)(blockRow + r0) * F_DIM + kq;
    float xn = 0.f;

    // B copy: 2048 16B slots / 512 threads = 4 per thread; slot s: row=s>>4, col16=s&15
    // ---- prologue: chunk 0 into stage 0 ----
    {
        const char* sw = (const char*)g_wh;
        #pragma unroll
        for (int o = 0; o < 4; ++o) {
            int s = tid + o * 512;
            uint32_t d0 = sb + B_BY + (uint32_t)(s >> 4) * RS_BY + (uint32_t)(s & 15) * 16;
            CPA16(d0, sw + s * 16);
        }
        CP_COMMIT();
        char* ap = smc + A_BY + r0 * RS_BY + kq * 2;
        #pragma unroll
        for (int j = 0; j < 4; ++j) {
            float4 v0 = *(const float4*)(xrow + j * 8);
            float4 v1 = *(const float4*)(xrow + j * 8 + 4);
            xn += conv8h(v0, v1, ap + j * 16);
        }
        CP_WAIT0();
    }
    __syncthreads();

    const uint32_t a_off = (uint32_t)((((lane >> 3) & 1) * 8 + (lane & 7)) * RS_BY
                                      + (lane >> 4) * 16);
    const uint32_t b_off = (uint32_t)(((lane >> 4) * 8 + (lane & 7)) * RS_BY
                                      + ((lane >> 3) & 1) * 16);
    const uint32_t a_row_by = (uint32_t)(wid_m * 32) * RS_BY;
    const uint32_t b_row_by = (uint32_t)(wid_n * 32) * RS_BY;

    float acc[2][4][4];
    #pragma unroll
    for (int i = 0; i < 2; ++i)
        #pragma unroll
        for (int j = 0; j < 4; ++j)
            #pragma unroll
            for (int k = 0; k < 4; ++k) acc[i][j][k] = 0.f;

    float4 pA[8];

    #pragma unroll 1
    for (int c = 0; c < NCHUNK; ++c) {
        const int cur = c & 1;
        const uint32_t nbase = sb + (cur ^ 1) * STAGE_BY;

        // ---- prefetch chunk c+1 (async B + x LDGs) before MMA section ----
        if (c < NCHUNK - 1) {
            const char* sw = (const char*)g_wh + (c + 1) * WCH_BY;
            #pragma unroll
            for (int o = 0; o < 4; ++o) {
                int s = tid + o * 512;
                uint32_t d0 = nbase + B_BY + (uint32_t)(s >> 4) * RS_BY + (uint32_t)(s & 15) * 16;
                CPA16(d0, sw + s * 16);
            }
            CP_COMMIT();
            const float* src = xrow + (c + 1) * KC;
            #pragma unroll
            for (int i = 0; i < 8; ++i) pA[i] = *(const float4*)(src + i * 4);
        }

        // ---- MMA over current stage: 8 ks x (4 LDSM + 16 MMA) ----
        const uint32_t sbase = sb + cur * STAGE_BY;
        #pragma unroll
        for (int ks = 0; ks < 8; ++ks) {
            const uint32_t kby = ks * 32;
            uint32_t am[2][4], bm[2][4];
            #pragma unroll
            for (int mb = 0; mb < 2; ++mb) {
                LDSM4(am[mb], sbase + A_BY + a_row_by + mb * 16 * RS_BY + kby + a_off);
            }
            #pragma unroll
            for (int nb = 0; nb < 2; ++nb) {
                LDSM4(bm[nb], sbase + B_BY + b_row_by + nb * 16 * RS_BY + kby + b_off);
            }
            #pragma unroll
            for (int mb = 0; mb < 2; ++mb)
                #pragma unroll
                for (int nf = 0; nf < 4; ++nf) {
                    const int nb = nf >> 1, h = (nf & 1) << 1;
                    MMA(acc[mb][nf], am[mb], bm[nb][h], bm[nb][h + 1]);
                }
        }

        // ---- convert prefetched x into next stage ----
        if (c < NCHUNK - 1) {
            char* ap = smc + (cur ^ 1) * STAGE_BY + A_BY + r0 * RS_BY + kq * 2;
            #pragma unroll
            for (int j = 0; j < 4; ++j) {
                xn += conv8h(pA[2 * j], pA[2 * j + 1], ap + j * 16);
            }
        }
        CP_WAIT0();
        __syncthreads();
    }

    // ---------------- finalize xnorm (deterministic tree) -------------------
    smf[XPART_OFF + r0 * 4 + (tid & 3)] = xn;
    __syncthreads();
    if (tid < 128) {
        float s = smf[XPART_OFF + tid * 4 + 0] + smf[XPART_OFF + tid * 4 + 1]
                + smf[XPART_OFF + tid * 4 + 2] + smf[XPART_OFF + tid * 4 + 3];
        smf[XNORM_OFF + tid] = s;
    }
    __syncthreads();

    // ---------------- Epilogue: si -> SARR ----------------
    #pragma unroll
    for (int mb = 0; mb < 2; ++mb) {
        const int rA = wid_m * 32 + mb * 16 + (lane >> 2);
        const float xnA = smf[XNORM_OFF + rA];
        const float xnB = smf[XNORM_OFF + rA + 8];
        #pragma unroll
        for (int nf = 0; nf < 4; ++nf) {
            const int cl = wid_n * 32 + nf * 8 + ((lane & 3) << 1);
            const float wn0 = smf[WNORM_OFF + cl], wn1 = smf[WNORM_OFF + cl + 1];
            const float g0 = smf[GAMMA_OFF + cl], g1 = smf[GAMMA_OFF + cl + 1];
            const float al0 = smf[ALPHA_OFF + cl], al1 = smf[ALPHA_OFF + cl + 1];
            float d00 = xnA + wn0 - 2.0f * acc[mb][nf][0];
            float d01 = xnA + wn1 - 2.0f * acc[mb][nf][1];
            float d10 = xnB + wn0 - 2.0f * acc[mb][nf][2];
            float d11 = xnB + wn1 - 2.0f * acc[mb][nf][3];
            smf[SARR_OFF + rA * SARR_STRIDE + cl]           = al0 * __expf(-g0 * d00);
            smf[SARR_OFF + rA * SARR_STRIDE + cl + 1]       = al1 * __expf(-g1 * d01);
            smf[SARR_OFF + (rA + 8) * SARR_STRIDE + cl]     = al0 * __expf(-g0 * d10);
            smf[SARR_OFF + (rA + 8) * SARR_STRIDE + cl + 1] = al1 * __expf(-g1 * d11);
        }
    }
    __syncthreads();

    // ---------------- DS scan: packed f32x2, one thread per row -------------
    if (tid < 128) {
        const int r = tid;
        const float4* srow = (const float4*)&smf[SARR_OFF + r * SARR_STRIDE];
        const float*  uT   = &smf[U_OFF];

        float mx = 0.f;
        #pragma unroll 8
        for (int i = 0; i < 32; ++i) {
            float4 v = srow[i];
            mx = fmaxf(mx, fmaxf(fmaxf(v.x, v.y), fmaxf(v.z, v.w)));
        }
        const float invm = 1.0f / (mx + 1e-4f);

        uint64_t q[5];
        float o1;
        float4 sv = srow[0];
        {
            float s0 = sv.x * invm;
            uint64_t s2 = pk2(s0, s0);
            const ulonglong2 ua = *(const ulonglong2*)(uT + 0);
            const ulonglong2 ub = *(const ulonglong2*)(uT + 4);
            const uint64_t  uc = *(const uint64_t*)(uT + 8);
            q[0] = mul2(ua.x, s2); q[1] = mul2(ua.y, s2);
            q[2] = mul2(ub.x, s2); q[3] = mul2(ub.y, s2);
            q[4] = mul2(uc,   s2);
            o1 = 1.0f - s0;
        }

        #define DS_STEP(P, SRAW, RENORM)                                          \
        {                                                                         \
            const float s  = (SRAW) * invm;                                       \
            const float o2 = 1.0f - s;                                            \
            const float rr = o1 * s;                                              \
            const uint64_t s2  = pk2(s,  s);                                      \
            const uint64_t o22 = pk2(o2, o2);                                     \
            const uint64_t r2  = pk2(rr, rr);                                     \
            const float* ub_ = uT + (P) * 12;                                     \
            const ulonglong2 ua = *(const ulonglong2*)(ub_);                      \
            const ulonglong2 ubp = *(const ulonglong2*)(ub_ + 4);                 \
            const uint64_t  ucp = *(const uint64_t*)(ub_ + 8);                    \
            uint64_t up[5] = { ua.x, ua.y, ubp.x, ubp.y, ucp };                   \
            _Pragma("unroll")                                                     \
            for (int k5 = 0; k5 < 5; ++k5) {                                      \
                uint64_t t = fma2(up[k5], s2, o22);                               \
                uint64_t w = mul2(r2, up[k5]);                                    \
                q[k5] = fma2(q[k5], t, w);                                        \
            }                                                                     \
            float o1n = 3.0f * (o1 * o2);                                         \
            if (RENORM) {                                                         \
                uint64_t ss = add2(add2(q[0], q[1]),                              \
                                   add2(add2(q[2], q[3]), q[4]));                 \
                float slo, shi; unpk2(ss, slo, shi);                              \
                float csum = slo + shi + o1n;                                     \
                float inv = __fdividef(1.0f, csum);                               \
                uint64_t inv2 = pk2(inv, inv);                                    \
                _Pragma("unroll")                                                 \
                for (int k5 = 0; k5 < 5; ++k5) q[k5] = mul2(q[k5], inv2);         \
                o1n *= inv;                                                       \
            }                                                                     \
            o1 = o1n;                                                             \
        }

        DS_STEP(1, sv.y, false)
        DS_STEP(2, sv.z, false)
        DS_STEP(3, sv.w, false)
        #pragma unroll 1
        for (int g = 1; g < 32; ++g) {
            sv = srow[g];
            const int p0 = g * 4;
            DS_STEP(p0 + 0, sv.x, true)
            DS_STEP(p0 + 1, sv.y, false)
            DS_STEP(p0 + 2, sv.z, false)
            DS_STEP(p0 + 3, sv.w, false)
        }
        #undef DS_STEP

        {
            uint64_t ss = add2(add2(q[0], q[1]), add2(add2(q[2], q[3]), q[4]));
            float slo, shi; unpk2(ss, slo, shi);
            float tot = slo + shi + o1;
            float inv = 1.0f / tot;
            float* op = out + (size_t)(blockRow + r) * (C_DIM + 1);
            #pragma unroll
            for (int k5 = 0; k5 < 5; ++k5) {
                float a, b; unpk2(q[k5], a, b);
                op[k5 * 2]     = a * inv;
                op[k5 * 2 + 1] = b * inv;
            }
            op[C_DIM] = o1 * inv;
        }
    }
}

extern "C" void kernel_launch(void* const* d_in, const int* in_sizes, int n_in,
                              void* d_out, int out_size)
{
    const float* x    = (const float*)d_in[0];
    const float* w    = (const float*)d_in[1];
    const float* eta  = (const float*)d_in[2];
    const float* xi   = (const float*)d_in[3];
    const float* beta = (const float*)d_in[4];
    float* out = (float*)d_out;

    prep_kernel<<<128, 128>>>(w, eta, xi, beta);

    cudaFuncSetAttribute(ds_mma_kernel,
                         cudaFuncAttributeMaxDynamicSharedMemorySize, SMEM_ALLOC);
    ds_mma_kernel<<<B_TOTAL / MT, THREADS, SMEM_ALLOC>>>(x, out);
}

// round 15
// speedup vs baseline: 1.0045x; 1.0045x over previous
#include <cuda_runtime.h>
#include <cuda_fp16.h>
#include <cstdint>
#include <math.h>

#define B_TOTAL 16384
#define F_DIM   512
#define P_DIM   128
#define C_DIM   10
#define MT      128
#define KC      64
#define NCHUNK  8
#define THREADS 512

// fp16 tile rows: 64 elems = 128B + 16B pad -> 144B stride (ldmatrix conflict-free)
#define RS_BY   144
#define TILE_BY (128 * RS_BY)            // 18432 B
#define STAGE_BY (2 * TILE_BY)           // 36864 B : A | B
#define A_BY    0
#define B_BY    TILE_BY

#define SARR_OFF    0
#define SARR_STRIDE 132                            // float4-aligned, conflict-free
#define U_OFF       (2 * STAGE_BY / 4)             // 18432 floats (after 2 stages)
#define UT_FLOATS   (P_DIM * 12)                   // 1536
#define XNORM_OFF   (U_OFF + UT_FLOATS)
#define WNORM_OFF   (XNORM_OFF + 128)
#define GAMMA_OFF   (WNORM_OFF + 128)
#define ALPHA_OFF   (GAMMA_OFF + 128)
#define XPART_OFF   (ALPHA_OFF + 128)
#define SMEM_FLOATS (XPART_OFF + 1024)
#define SMEM_ALLOC  (SMEM_FLOATS * 4 + 1024)

// w chunk tile: 128 rows x 64 fp16 = 16384 B
#define WCH_BY 16384

__device__ __align__(256) __half g_wh[NCHUNK * P_DIM * KC];
__device__ float g_params[384 + UT_FLOATS];   // wnorm|gamma|alpha|uT(p-major,pad12)

__device__ __forceinline__ uint32_t smem_u32(const void* p) {
    uint32_t a;
    asm("{ .reg .u64 t; cvta.to.shared.u64 t, %1; cvt.u32.u64 %0, t; }"
        : "=r"(a) : "l"(p));
    return a;
}
__device__ __forceinline__ uint32_t pack_f16x2(float lo_elem, float hi_elem) {
    uint32_t r;
    asm("cvt.rn.f16x2.f32 %0, %1, %2;" : "=r"(r) : "f"(hi_elem), "f"(lo_elem));
    return r;
}
// ---- packed f32x2 helpers (sm_100+ base ISA) ----
__device__ __forceinline__ uint64_t pk2(float lo, float hi) {
    uint64_t d;
    asm("mov.b64 %0, {%1, %2};" : "=l"(d)
        : "r"(__float_as_uint(lo)), "r"(__float_as_uint(hi)));
    return d;
}
__device__ __forceinline__ void unpk2(uint64_t v, float& lo, float& hi) {
    uint32_t a, b;
    asm("mov.b64 {%0, %1}, %2;" : "=r"(a), "=r"(b) : "l"(v));
    lo = __uint_as_float(a); hi = __uint_as_float(b);
}
__device__ __forceinline__ uint64_t fma2(uint64_t a, uint64_t b, uint64_t c) {
    uint64_t d;
    asm("fma.rn.f32x2 %0, %1, %2, %3;" : "=l"(d) : "l"(a), "l"(b), "l"(c));
    return d;
}
__device__ __forceinline__ uint64_t mul2(uint64_t a, uint64_t b) {
    uint64_t d;
    asm("mul.rn.f32x2 %0, %1, %2;" : "=l"(d) : "l"(a), "l"(b));
    return d;
}
__device__ __forceinline__ uint64_t add2(uint64_t a, uint64_t b) {
    uint64_t d;
    asm("add.rn.f32x2 %0, %1, %2;" : "=l"(d) : "l"(a), "l"(b));
    return d;
}

#define LDSM4(r, addr) \
    asm volatile("ldmatrix.sync.aligned.m8n8.x4.shared.b16 {%0,%1,%2,%3}, [%4];" \
        : "=r"((r)[0]), "=r"((r)[1]), "=r"((r)[2]), "=r"((r)[3]) : "r"(addr))
#define MMA(acc, a, b0, b1) \
    asm volatile("mma.sync.aligned.m16n8k16.row.col.f32.f16.f16.f32 " \
        "{%0,%1,%2,%3}, {%4,%5,%6,%7}, {%8,%9}, {%0,%1,%2,%3};" \
        : "+f"((acc)[0]), "+f"((acc)[1]), "+f"((acc)[2]), "+f"((acc)[3]) \
        : "r"((a)[0]), "r"((a)[1]), "r"((a)[2]), "r"((a)[3]), "r"(b0), "r"(b1))
#define CPA16(dst, src) \
    asm volatile("cp.async.cg.shared.global [%0], [%1], 16;" :: "r"(dst), "l"(src) : "memory")
#define CP_COMMIT() asm volatile("cp.async.commit_group;" ::: "memory")
#define CP_WAIT0()  asm volatile("cp.async.wait_group 0;" ::: "memory")

// convert 8 fp32 (regs) -> 8 fp16 (RN); returns fp32 sum of squares
__device__ __forceinline__ float conv8h(float4 v0, float4 v1, char* dst) {
    uint4 h;
    h.x = pack_f16x2(v0.x, v0.y);
    h.y = pack_f16x2(v0.z, v0.w);
    h.z = pack_f16x2(v1.x, v1.y);
    h.w = pack_f16x2(v1.z, v1.w);
    *(uint4*)dst = h;
    return v0.x*v0.x + v0.y*v0.y + v0.z*v0.z + v0.w*v0.w
         + v1.x*v1.x + v1.y*v1.y + v1.z*v1.z + v1.w*v1.w;
}

// ------------------------- prep kernel: w -> fp16 + params ------------------
__global__ __launch_bounds__(128)
void prep_kernel(const float* __restrict__ w,
                 const float* __restrict__ eta,
                 const float* __restrict__ xi,
                 const float* __restrict__ beta)
{
    __shared__ float sred[128];
    const int p = blockIdx.x;
    const int t = threadIdx.x;
    float4 v = ((const float4*)(w + (size_t)p * F_DIM))[t];
    uint32_t h0 = pack_f16x2(v.x, v.y);
    uint32_t h1 = pack_f16x2(v.z, v.w);
    const int c = t >> 4;
    const int k = (t & 15) << 2;
    const int idx = c * (P_DIM * KC) + p * KC + k;
    *(uint2*)&g_wh[idx] = make_uint2(h0, h1);

    sred[t] = v.x*v.x + v.y*v.y + v.z*v.z + v.w*v.w;
    __syncthreads();
    #pragma unroll
    for (int o = 64; o > 0; o >>= 1) {
        if (t < o) sred[t] += sred[t + o];
        __syncthreads();
    }
    if (t == 0) {
        g_params[p] = sred[0];
        float e = eta[p];
        g_params[128 + p] = e * e;
        g_params[256 + p] = 1.0f / (1.0f + expf(-xi[p]));
        float b2[C_DIM]; float bs = 0.f;
        #pragma unroll
        for (int cc = 0; cc < C_DIM; ++cc) {
            float bv = beta[cc * P_DIM + p];
            b2[cc] = bv * bv; bs += b2[cc];
        }
        float binv = 1.0f / bs;
        #pragma unroll
        for (int cc = 0; cc < C_DIM; ++cc)
            g_params[384 + p * 12 + cc] = b2[cc] * binv;
        g_params[384 + p * 12 + 10] = 0.f;   // zero pad -> h1's third pack is exactly 0
        g_params[384 + p * 12 + 11] = 0.f;
    }
}

// ------------------------------- main kernel --------------------------------
__global__ __launch_bounds__(THREADS, 1)
void ds_mma_kernel(const float* __restrict__ x,
                   float* __restrict__ out)
{
    extern __shared__ char dsm[];
    uintptr_t ga = ((uintptr_t)dsm + 1023) & ~(uintptr_t)1023;
    float* smf = (float*)ga;
    char*  smc = (char*)ga;
    const uint32_t sb = smem_u32(smf);

    const int tid  = threadIdx.x;
    const int lane = tid & 31;
    const int wid  = tid >> 5;
    const int wid_m = wid >> 2;
    const int wid_n = wid & 3;
    const int blockRow = blockIdx.x * MT;

    // params -> smem
    #pragma unroll
    for (int i = tid; i < 384; i += THREADS) smf[WNORM_OFF + i] = g_params[i];
    #pragma unroll
    for (int i = tid; i < UT_FLOATS; i += THREADS) smf[U_OFF + i] = g_params[384 + i];

    const int r0 = tid >> 3;
    const int kq = (tid & 7) << 3;
    const float* xrow0 = x + (size_t)(blockRow + r0) * F_DIM + kq;
    const float* xrow1 = x + (size_t)(blockRow + r0 + 64) * F_DIM + kq;
    float xn0 = 0.f, xn1 = 0.f;

    // ---- prologue: chunk 0 into stage 0 ----
    {
        const char* sw = (const char*)g_wh;
        #pragma unroll
        for (int o = 0; o < 2; ++o) {
            int s = tid + o * 512;
            uint32_t d0 = sb + B_BY + (uint32_t)(s >> 3) * RS_BY + (uint32_t)(s & 7) * 16;
            CPA16(d0, sw + s * 16);
        }
        CP_COMMIT();
        float4 a0 = *(const float4*)(xrow0);
        float4 a1 = *(const float4*)(xrow0 + 4);
        float4 a2 = *(const float4*)(xrow1);
        float4 a3 = *(const float4*)(xrow1 + 4);
        xn0 += conv8h(a0, a1, smc + A_BY + r0 * RS_BY + kq * 2);
        xn1 += conv8h(a2, a3, smc + A_BY + (r0 + 64) * RS_BY + kq * 2);
        CP_WAIT0();
    }
    __syncthreads();

    const uint32_t a_off = (uint32_t)((((lane >> 3) & 1) * 8 + (lane & 7)) * RS_BY
                                      + (lane >> 4) * 16);
    const uint32_t b_off = (uint32_t)(((lane >> 4) * 8 + (lane & 7)) * RS_BY
                                      + ((lane >> 3) & 1) * 16);
    const uint32_t a_row_by = (uint32_t)(wid_m * 32) * RS_BY;
    const uint32_t b_row_by = (uint32_t)(wid_n * 32) * RS_BY;

    float acc[2][4][4];
    #pragma unroll
    for (int i = 0; i < 2; ++i)
        #pragma unroll
        for (int j = 0; j < 4; ++j)
            #pragma unroll
            for (int k = 0; k < 4; ++k) acc[i][j][k] = 0.f;

    float4 pA0, pA1, pA2, pA3;

    #pragma unroll 1
    for (int c = 0; c < NCHUNK; ++c) {
        const int cur = c & 1;
        const uint32_t nbase = sb + (cur ^ 1) * STAGE_BY;

        // ---- prefetch chunk c+1 (async B + x LDGs) before MMA section ----
        if (c < NCHUNK - 1) {
            const char* sw = (const char*)g_wh + (c + 1) * WCH_BY;
            #pragma unroll
            for (int o = 0; o < 2; ++o) {
                int s = tid + o * 512;
                uint32_t d0 = nbase + B_BY + (uint32_t)(s >> 3) * RS_BY + (uint32_t)(s & 7) * 16;
                CPA16(d0, sw + s * 16);
            }
            CP_COMMIT();
            const int kb = (c + 1) * KC;
            pA0 = *(const float4*)(xrow0 + kb);
            pA1 = *(const float4*)(xrow0 + kb + 4);
            pA2 = *(const float4*)(xrow1 + kb);
            pA3 = *(const float4*)(xrow1 + kb + 4);
        }

        // ---- MMA over current stage: 4 ks x (4 LDSM + 16 MMA) ----
        const uint32_t sbase = sb + cur * STAGE_BY;
        #pragma unroll
        for (int ks = 0; ks < 4; ++ks) {
            const uint32_t kby = ks * 32;
            uint32_t am[2][4], bm[2][4];
            #pragma unroll
            for (int mb = 0; mb < 2; ++mb) {
                uint32_t base = sbase + a_row_by + mb * 16 * RS_BY + kby + a_off;
                LDSM4(am[mb], base + A_BY);
            }
            #pragma unroll
            for (int nb = 0; nb < 2; ++nb) {
                uint32_t base = sbase + b_row_by + nb * 16 * RS_BY + kby + b_off;
                LDSM4(bm[nb], base + B_BY);
            }
            #pragma unroll
            for (int mb = 0; mb < 2; ++mb)
                #pragma unroll
                for (int nf = 0; nf < 4; ++nf) {
                    const int nb = nf >> 1, h = (nf & 1) << 1;
                    MMA(acc[mb][nf], am[mb], bm[nb][h], bm[nb][h + 1]);
                }
        }

        // ---- convert prefetched x into next stage ----
        if (c < NCHUNK - 1) {
            char* np = smc + (cur ^ 1) * STAGE_BY;
            xn0 += conv8h(pA0, pA1, np + A_BY + r0 * RS_BY + kq * 2);
            xn1 += conv8h(pA2, pA3, np + A_BY + (r0 + 64) * RS_BY + kq * 2);
        }
        CP_WAIT0();
        __syncthreads();
    }

    // ---------------- finalize xnorm (deterministic tree) -------------------
    smf[XPART_OFF + r0 * 8 + (tid & 7)] = xn0;
    smf[XPART_OFF + (r0 + 64) * 8 + (tid & 7)] = xn1;
    __syncthreads();
    if (tid < 128) {
        float s = 0.f;
        #pragma unroll
        for (int q = 0; q < 8; ++q) s += smf[XPART_OFF + tid * 8 + q];
        smf[XNORM_OFF + tid] = s;
    }
    __syncthreads();

    // ---------------- Epilogue: si -> SARR ----------------
    #pragma unroll
    for (int mb = 0; mb < 2; ++mb) {
        const int rA = wid_m * 32 + mb * 16 + (lane >> 2);
        const float xnA = smf[XNORM_OFF + rA];
        const float xnB = smf[XNORM_OFF + rA + 8];
        #pragma unroll
        for (int nf = 0; nf < 4; ++nf) {
            const int cl = wid_n * 32 + nf * 8 + ((lane & 3) << 1);
            const float wn0 = smf[WNORM_OFF + cl], wn1 = smf[WNORM_OFF + cl + 1];
            const float g0 = smf[GAMMA_OFF + cl], g1 = smf[GAMMA_OFF + cl + 1];
            const float al0 = smf[ALPHA_OFF + cl], al1 = smf[ALPHA_OFF + cl + 1];
            float d00 = xnA + wn0 - 2.0f * acc[mb][nf][0];
            float d01 = xnA + wn1 - 2.0f * acc[mb][nf][1];
            float d10 = xnB + wn0 - 2.0f * acc[mb][nf][2];
            float d11 = xnB + wn1 - 2.0f * acc[mb][nf][3];
            smf[SARR_OFF + rA * SARR_STRIDE + cl]           = al0 * __expf(-g0 * d00);
            smf[SARR_OFF + rA * SARR_STRIDE + cl + 1]       = al1 * __expf(-g1 * d01);
            smf[SARR_OFF + (rA + 8) * SARR_STRIDE + cl]     = al0 * __expf(-g0 * d10);
            smf[SARR_OFF + (rA + 8) * SARR_STRIDE + cl + 1] = al1 * __expf(-g1 * d11);
        }
    }
    __syncthreads();

    // ---------- DS scan: pair-split f32x2, 2 threads per row (8 warps) ------
    if (tid < 256) {
        const int r = tid >> 1;           // row
        const int h = tid & 1;            // half: 0 -> classes 0..5, 1 -> 6..9 (+zero pad)
        const int poff = h * 6;           // float offset of this half's packs in uT row
        const float4* srow = (const float4*)&smf[SARR_OFF + r * SARR_STRIDE];
        const float*  uT   = &smf[U_OFF];

        // split row-max: 16 float4 each, combine across the pair
        float mx = 0.f;
        #pragma unroll 4
        for (int i = h * 16; i < h * 16 + 16; ++i) {
            float4 v = srow[i];
            mx = fmaxf(mx, fmaxf(fmaxf(v.x, v.y), fmaxf(v.z, v.w)));
        }
        mx = fmaxf(mx, __shfl_xor_sync(0xFFFFFFFFu, mx, 1));
        const float invm = 1.0f / (mx + 1e-4f);

        uint64_t q[3];
        float o1;                          // both halves maintain o1 redundantly
        float4 sv = srow[0];
        {
            float s0 = sv.x * invm;
            uint64_t s2 = pk2(s0, s0);
            #pragma unroll
            for (int k5 = 0; k5 < 3; ++k5) {
                uint64_t up = *(const uint64_t*)(uT + poff + 2 * k5);
                q[k5] = mul2(up, s2);
            }
            o1 = 1.0f - s0;
        }

        #define DS_STEP2(P, SRAW, RENORM)                                         \
        {                                                                         \
            const float s  = (SRAW) * invm;                                       \
            const float o2 = 1.0f - s;                                            \
            const float rr = o1 * s;                                              \
            const uint64_t s2  = pk2(s,  s);                                      \
            const uint64_t o22 = pk2(o2, o2);                                     \
            const uint64_t r2  = pk2(rr, rr);                                     \
            const float* ub_ = uT + (P) * 12 + poff;                              \
            _Pragma("unroll")                                                     \
            for (int k5 = 0; k5 < 3; ++k5) {                                      \
                uint64_t up = *(const uint64_t*)(ub_ + 2 * k5);                   \
                q[k5] = fma2(q[k5], fma2(up, s2, o22), mul2(r2, up));             \
            }                                                                     \
            float o1n = 3.0f * (o1 * o2);                                         \
            if (RENORM) {                                                         \
                uint64_t ss = add2(add2(q[0], q[1]), q[2]);                       \
                float slo, shi; unpk2(ss, slo, shi);                              \
                float ps = slo + shi;                                             \
                float po = __shfl_xor_sync(0xFFFFFFFFu, ps, 1);                   \
                float csum = ps + po + o1n;                                       \
                float inv = __fdividef(1.0f, csum);                               \
                uint64_t inv2 = pk2(inv, inv);                                    \
                _Pragma("unroll")                                                 \
                for (int k5 = 0; k5 < 3; ++k5) q[k5] = mul2(q[k5], inv2);         \
                o1n *= inv;                                                       \
            }                                                                     \
            o1 = o1n;                                                             \
        }

        DS_STEP2(1, sv.y, false)
        DS_STEP2(2, sv.z, false)
        DS_STEP2(3, sv.w, false)
        #pragma unroll 1
        for (int g = 1; g < 32; ++g) {
            sv = srow[g];
            const int p0 = g * 4;
            DS_STEP2(p0 + 0, sv.x, true)
            DS_STEP2(p0 + 1, sv.y, false)
            DS_STEP2(p0 + 2, sv.z, false)
            DS_STEP2(p0 + 3, sv.w, false)
        }
        #undef DS_STEP2

        // final normalize: exchange partial sums, each half writes its classes
        {
            uint64_t ss = add2(add2(q[0], q[1]), q[2]);
            float slo, shi; unpk2(ss, slo, shi);
            float ps = slo + shi;
            float po = __shfl_xor_sync(0xFFFFFFFFu, ps, 1);
            float tot = ps + po + o1;
            float inv = 1.0f / tot;
            float* op = out + (size_t)(blockRow + r) * (C_DIM + 1);
            if (h == 0) {
                #pragma unroll
                for (int k5 = 0; k5 < 3; ++k5) {
                    float a, b; unpk2(q[k5], a, b);
                    op[k5 * 2]     = a * inv;
                    op[k5 * 2 + 1] = b * inv;
                }
            } else {
                #pragma unroll
                for (int k5 = 0; k5 < 2; ++k5) {
                    float a, b; unpk2(q[k5], a, b);
                    op[6 + k5 * 2]     = a * inv;
                    op[6 + k5 * 2 + 1] = b * inv;
                }
                op[C_DIM] = o1 * inv;
            }
        }
    }
}

extern "C" void kernel_launch(void* const* d_in, const int* in_sizes, int n_in,
                              void* d_out, int out_size)
{
    const float* x    = (const float*)d_in[0];
    const float* w    = (const float*)d_in[1];
    const float* eta  = (const float*)d_in[2];
    const float* xi   = (const float*)d_in[3];
    const float* beta = (const float*)d_in[4];
    float* out = (float*)d_out;

    prep_kernel<<<128, 128>>>(w, eta, xi, beta);

    cudaFuncSetAttribute(ds_mma_kernel,
                         cudaFuncAttributeMaxDynamicSharedMemorySize, SMEM_ALLOC);
    ds_mma_kernel<<<B_TOTAL / MT, THREADS, SMEM_ALLOC>>>(x, out);
}

// round 16
// speedup vs baseline: 1.6088x; 1.6017x over previous
#include <cuda_runtime.h>
#include <cuda_fp16.h>
#include <cstdint>
#include <math.h>

#define B_TOTAL 16384
#define F_DIM   512
#define P_DIM   128
#define C_DIM   10
#define MT      128
#define KC      64
#define NCHUNK  8
#define THREADS 512

// fp16 tile rows: 64 elems = 128B + 16B pad -> 144B stride (ldmatrix conflict-free)
#define RS_BY   144
#define TILE_BY (128 * RS_BY)            // 18432 B
#define STAGE_BY (2 * TILE_BY)           // 36864 B : A | B
#define A_BY    0
#define B_BY    TILE_BY

#define SARR_OFF    0
#define SARR_STRIDE 132                            // float4-aligned, conflict-free
#define U_OFF       (2 * STAGE_BY / 4)             // 18432 floats (after 2 stages)
#define UT_FLOATS   (P_DIM * 12)                   // 1536
#define XNORM_OFF   (U_OFF + UT_FLOATS)
#define WNORM_OFF   (XNORM_OFF + 128)
#define GAMMA_OFF   (WNORM_OFF + 128)
#define ALPHA_OFF   (GAMMA_OFF + 128)
#define XPART_OFF   (ALPHA_OFF + 128)
#define RMAX_OFF    (XPART_OFF + 1024)
#define SMEM_FLOATS (RMAX_OFF + 128)
#define SMEM_ALLOC  (SMEM_FLOATS * 4 + 1024)

// w chunk tile: 128 rows x 64 fp16 = 16384 B
#define WCH_BY 16384

__device__ __align__(256) __half g_wh[NCHUNK * P_DIM * KC];
__device__ float g_params[384 + UT_FLOATS];   // wnorm|gamma|alpha|uT(p-major,pad12)

__device__ __forceinline__ uint32_t smem_u32(const void* p) {
    uint32_t a;
    asm("{ .reg .u64 t; cvta.to.shared.u64 t, %1; cvt.u32.u64 %0, t; }"
        : "=r"(a) : "l"(p));
    return a;
}
__device__ __forceinline__ uint32_t pack_f16x2(float lo_elem, float hi_elem) {
    uint32_t r;
    asm("cvt.rn.f16x2.f32 %0, %1, %2;" : "=r"(r) : "f"(hi_elem), "f"(lo_elem));
    return r;
}
// ---- packed f32x2 helpers (sm_100+ base ISA) ----
__device__ __forceinline__ uint64_t pk2(float lo, float hi) {
    uint64_t d;
    asm("mov.b64 %0, {%1, %2};" : "=l"(d)
        : "r"(__float_as_uint(lo)), "r"(__float_as_uint(hi)));
    return d;
}
__device__ __forceinline__ void unpk2(uint64_t v, float& lo, float& hi) {
    uint32_t a, b;
    asm("mov.b64 {%0, %1}, %2;" : "=r"(a), "=r"(b) : "l"(v));
    lo = __uint_as_float(a); hi = __uint_as_float(b);
}
__device__ __forceinline__ uint64_t fma2(uint64_t a, uint64_t b, uint64_t c) {
    uint64_t d;
    asm("fma.rn.f32x2 %0, %1, %2, %3;" : "=l"(d) : "l"(a), "l"(b), "l"(c));
    return d;
}
__device__ __forceinline__ uint64_t mul2(uint64_t a, uint64_t b) {
    uint64_t d;
    asm("mul.rn.f32x2 %0, %1, %2;" : "=l"(d) : "l"(a), "l"(b));
    return d;
}
__device__ __forceinline__ uint64_t add2(uint64_t a, uint64_t b) {
    uint64_t d;
    asm("add.rn.f32x2 %0, %1, %2;" : "=l"(d) : "l"(a), "l"(b));
    return d;
}

#define LDSM4(r, addr) \
    asm volatile("ldmatrix.sync.aligned.m8n8.x4.shared.b16 {%0,%1,%2,%3}, [%4];" \
        : "=r"((r)[0]), "=r"((r)[1]), "=r"((r)[2]), "=r"((r)[3]) : "r"(addr))
#define MMA(acc, a, b0, b1) \
    asm volatile("mma.sync.aligned.m16n8k16.row.col.f32.f16.f16.f32 " \
        "{%0,%1,%2,%3}, {%4,%5,%6,%7}, {%8,%9}, {%0,%1,%2,%3};" \
        : "+f"((acc)[0]), "+f"((acc)[1]), "+f"((acc)[2]), "+f"((acc)[3]) \
        : "r"((a)[0]), "r"((a)[1]), "r"((a)[2]), "r"((a)[3]), "r"(b0), "r"(b1))
#define CPA16(dst, src) \
    asm volatile("cp.async.cg.shared.global [%0], [%1], 16;" :: "r"(dst), "l"(src) : "memory")
#define CP_COMMIT() asm volatile("cp.async.commit_group;" ::: "memory")
#define CP_WAIT0()  asm volatile("cp.async.wait_group 0;" ::: "memory")

// convert 8 fp32 (regs) -> 8 fp16 (RN); returns fp32 sum of squares
__device__ __forceinline__ float conv8h(float4 v0, float4 v1, char* dst) {
    uint4 h;
    h.x = pack_f16x2(v0.x, v0.y);
    h.y = pack_f16x2(v0.z, v0.w);
    h.z = pack_f16x2(v1.x, v1.y);
    h.w = pack_f16x2(v1.z, v1.w);
    *(uint4*)dst = h;
    return v0.x*v0.x + v0.y*v0.y + v0.z*v0.z + v0.w*v0.w
         + v1.x*v1.x + v1.y*v1.y + v1.z*v1.z + v1.w*v1.w;
}

// ------------------------- prep kernel: w -> fp16 + params ------------------
__global__ __launch_bounds__(128)
void prep_kernel(const float* __restrict__ w,
                 const float* __restrict__ eta,
                 const float* __restrict__ xi,
                 const float* __restrict__ beta)
{
    __shared__ float sred[128];
    const int p = blockIdx.x;
    const int t = threadIdx.x;
    float4 v = ((const float4*)(w + (size_t)p * F_DIM))[t];
    uint32_t h0 = pack_f16x2(v.x, v.y);
    uint32_t h1 = pack_f16x2(v.z, v.w);
    const int c = t >> 4;
    const int k = (t & 15) << 2;
    const int idx = c * (P_DIM * KC) + p * KC + k;
    *(uint2*)&g_wh[idx] = make_uint2(h0, h1);

    sred[t] = v.x*v.x + v.y*v.y + v.z*v.z + v.w*v.w;
    __syncthreads();
    #pragma unroll
    for (int o = 64; o > 0; o >>= 1) {
        if (t < o) sred[t] += sred[t + o];
        __syncthreads();
    }
    if (t == 0) {
        g_params[p] = sred[0];
        float e = eta[p];
        g_params[128 + p] = e * e;
        g_params[256 + p] = 1.0f / (1.0f + expf(-xi[p]));
        float b2[C_DIM]; float bs = 0.f;
        #pragma unroll
        for (int cc = 0; cc < C_DIM; ++cc) {
            float bv = beta[cc * P_DIM + p];
            b2[cc] = bv * bv; bs += b2[cc];
        }
        float binv = 1.0f / bs;
        #pragma unroll
        for (int cc = 0; cc < C_DIM; ++cc)
            g_params[384 + p * 12 + cc] = b2[cc] * binv;
        g_params[384 + p * 12 + 10] = 0.f;
        g_params[384 + p * 12 + 11] = 0.f;
    }
}

// ------------------------------- main kernel --------------------------------
__global__ __launch_bounds__(THREADS, 1)
void ds_mma_kernel(const float* __restrict__ x,
                   float* __restrict__ out)
{
    extern __shared__ char dsm[];
    uintptr_t ga = ((uintptr_t)dsm + 1023) & ~(uintptr_t)1023;
    float* smf = (float*)ga;
    char*  smc = (char*)ga;
    const uint32_t sb = smem_u32(smf);

    const int tid  = threadIdx.x;
    const int lane = tid & 31;
    const int wid  = tid >> 5;
    const int wid_m = wid >> 2;
    const int wid_n = wid & 3;
    const int blockRow = blockIdx.x * MT;

    // params -> smem; RMAX init to 0
    #pragma unroll
    for (int i = tid; i < 384; i += THREADS) smf[WNORM_OFF + i] = g_params[i];
    #pragma unroll
    for (int i = tid; i < UT_FLOATS; i += THREADS) smf[U_OFF + i] = g_params[384 + i];
    if (tid < 128) smf[RMAX_OFF + tid] = 0.f;

    const int r0 = tid >> 3;
    const int kq = (tid & 7) << 3;
    const float* xrow0 = x + (size_t)(blockRow + r0) * F_DIM + kq;
    const float* xrow1 = x + (size_t)(blockRow + r0 + 64) * F_DIM + kq;
    float xn0 = 0.f, xn1 = 0.f;

    // ---- prologue: chunk 0 into stage 0 ----
    {
        const char* sw = (const char*)g_wh;
        #pragma unroll
        for (int o = 0; o < 2; ++o) {
            int s = tid + o * 512;
            uint32_t d0 = sb + B_BY + (uint32_t)(s >> 3) * RS_BY + (uint32_t)(s & 7) * 16;
            CPA16(d0, sw + s * 16);
        }
        CP_COMMIT();
        float4 a0 = *(const float4*)(xrow0);
        float4 a1 = *(const float4*)(xrow0 + 4);
        float4 a2 = *(const float4*)(xrow1);
        float4 a3 = *(const float4*)(xrow1 + 4);
        xn0 += conv8h(a0, a1, smc + A_BY + r0 * RS_BY + kq * 2);
        xn1 += conv8h(a2, a3, smc + A_BY + (r0 + 64) * RS_BY + kq * 2);
        CP_WAIT0();
    }
    __syncthreads();

    const uint32_t a_off = (uint32_t)((((lane >> 3) & 1) * 8 + (lane & 7)) * RS_BY
                                      + (lane >> 4) * 16);
    const uint32_t b_off = (uint32_t)(((lane >> 4) * 8 + (lane & 7)) * RS_BY
                                      + ((lane >> 3) & 1) * 16);
    const uint32_t a_row_by = (uint32_t)(wid_m * 32) * RS_BY;
    const uint32_t b_row_by = (uint32_t)(wid_n * 32) * RS_BY;

    float acc[2][4][4];
    #pragma unroll
    for (int i = 0; i < 2; ++i)
        #pragma unroll
        for (int j = 0; j < 4; ++j)
            #pragma unroll
            for (int k = 0; k < 4; ++k) acc[i][j][k] = 0.f;

    float4 pA0, pA1, pA2, pA3;

    #pragma unroll 1
    for (int c = 0; c < NCHUNK; ++c) {
        const int cur = c & 1;
        const uint32_t nbase = sb + (cur ^ 1) * STAGE_BY;

        // ---- prefetch chunk c+1 (async B + x LDGs) before MMA section ----
        if (c < NCHUNK - 1) {
            const char* sw = (const char*)g_wh + (c + 1) * WCH_BY;
            #pragma unroll
            for (int o = 0; o < 2; ++o) {
                int s = tid + o * 512;
                uint32_t d0 = nbase + B_BY + (uint32_t)(s >> 3) * RS_BY + (uint32_t)(s & 7) * 16;
                CPA16(d0, sw + s * 16);
            }
            CP_COMMIT();
            const int kb = (c + 1) * KC;
            pA0 = *(const float4*)(xrow0 + kb);
            pA1 = *(const float4*)(xrow0 + kb + 4);
            pA2 = *(const float4*)(xrow1 + kb);
            pA3 = *(const float4*)(xrow1 + kb + 4);
        }

        // ---- MMA over current stage: 4 ks x (4 LDSM + 16 MMA) ----
        const uint32_t sbase = sb + cur * STAGE_BY;
        #pragma unroll
        for (int ks = 0; ks < 4; ++ks) {
            const uint32_t kby = ks * 32;
            uint32_t am[2][4], bm[2][4];
            #pragma unroll
            for (int mb = 0; mb < 2; ++mb) {
                uint32_t base = sbase + a_row_by + mb * 16 * RS_BY + kby + a_off;
                LDSM4(am[mb], base + A_BY);
            }
            #pragma unroll
            for (int nb = 0; nb < 2; ++nb) {
                uint32_t base = sbase + b_row_by + nb * 16 * RS_BY + kby + b_off;
                LDSM4(bm[nb], base + B_BY);
            }
            #pragma unroll
            for (int mb = 0; mb < 2; ++mb)
                #pragma unroll
                for (int nf = 0; nf < 4; ++nf) {
                    const int nb = nf >> 1, h = (nf & 1) << 1;
                    MMA(acc[mb][nf], am[mb], bm[nb][h], bm[nb][h + 1]);
                }
        }

        // ---- convert prefetched x into next stage ----
        if (c < NCHUNK - 1) {
            char* np = smc + (cur ^ 1) * STAGE_BY;
            xn0 += conv8h(pA0, pA1, np + A_BY + r0 * RS_BY + kq * 2);
            xn1 += conv8h(pA2, pA3, np + A_BY + (r0 + 64) * RS_BY + kq * 2);
            CP_WAIT0();
        }
        __syncthreads();
    }

    // ---------------- finalize xnorm (deterministic tree) -------------------
    smf[XPART_OFF + r0 * 8 + (tid & 7)] = xn0;
    smf[XPART_OFF + (r0 + 64) * 8 + (tid & 7)] = xn1;
    __syncthreads();
    if (tid < 128) {
        float s = 0.f;
        #pragma unroll
        for (int q = 0; q < 8; ++q) s += smf[XPART_OFF + tid * 8 + q];
        smf[XNORM_OFF + tid] = s;
    }
    __syncthreads();

    // ------- Epilogue: si -> SARR + row max via positive-float atomicMax ----
    #pragma unroll
    for (int mb = 0; mb < 2; ++mb) {
        const int rA = wid_m * 32 + mb * 16 + (lane >> 2);
        const float xnA = smf[XNORM_OFF + rA];
        const float xnB = smf[XNORM_OFF + rA + 8];
        float mxA = 0.f, mxB = 0.f;
        #pragma unroll
        for (int nf = 0; nf < 4; ++nf) {
            const int cl = wid_n * 32 + nf * 8 + ((lane & 3) << 1);
            const float wn0 = smf[WNORM_OFF + cl], wn1 = smf[WNORM_OFF + cl + 1];
            const float g0 = smf[GAMMA_OFF + cl], g1 = smf[GAMMA_OFF + cl + 1];
            const float al0 = smf[ALPHA_OFF + cl], al1 = smf[ALPHA_OFF + cl + 1];
            float d00 = xnA + wn0 - 2.0f * acc[mb][nf][0];
            float d01 = xnA + wn1 - 2.0f * acc[mb][nf][1];
            float d10 = xnB + wn0 - 2.0f * acc[mb][nf][2];
            float d11 = xnB + wn1 - 2.0f * acc[mb][nf][3];
            float v00 = al0 * __expf(-g0 * d00);
            float v01 = al1 * __expf(-g1 * d01);
            float v10 = al0 * __expf(-g0 * d10);
            float v11 = al1 * __expf(-g1 * d11);
            smf[SARR_OFF + rA * SARR_STRIDE + cl]           = v00;
            smf[SARR_OFF + rA * SARR_STRIDE + cl + 1]       = v01;
            smf[SARR_OFF + (rA + 8) * SARR_STRIDE + cl]     = v10;
            smf[SARR_OFF + (rA + 8) * SARR_STRIDE + cl + 1] = v11;
            mxA = fmaxf(mxA, fmaxf(v00, v01));
            mxB = fmaxf(mxB, fmaxf(v10, v11));
        }
        // si >= 0, so int-compare == float-compare
        atomicMax((int*)&smf[RMAX_OFF + rA],     __float_as_int(mxA));
        atomicMax((int*)&smf[RMAX_OFF + rA + 8], __float_as_int(mxB));
    }
    __syncthreads();

    // ---------------- DS scan: packed f32x2, one thread per row -------------
    if (tid < 128) {
        const int r = tid;
        const float4* srow = (const float4*)&smf[SARR_OFF + r * SARR_STRIDE];
        const float*  uT   = &smf[U_OFF];

        const float invm = 1.0f / (smf[RMAX_OFF + r] + 1e-4f);

        uint64_t q[5];
        float o1;
        float4 sv = srow[0];
        {
            float s0 = sv.x * invm;
            uint64_t s2 = pk2(s0, s0);
            const ulonglong2 ua = *(const ulonglong2*)(uT + 0);
            const ulonglong2 ub = *(const ulonglong2*)(uT + 4);
            const uint64_t  uc = *(const uint64_t*)(uT + 8);
            q[0] = mul2(ua.x, s2); q[1] = mul2(ua.y, s2);
            q[2] = mul2(ub.x, s2); q[3] = mul2(ub.y, s2);
            q[4] = mul2(uc,   s2);
            o1 = 1.0f - s0;
        }

        #define DS_STEP(P, SRAW, RENORM)                                          \
        {                                                                         \
            const float s  = (SRAW) * invm;                                       \
            const float o2 = 1.0f - s;                                            \
            const float rr = o1 * s;                                              \
            const uint64_t s2  = pk2(s,  s);                                      \
            const uint64_t o22 = pk2(o2, o2);                                     \
            const uint64_t r2  = pk2(rr, rr);                                     \
            const float* ub_ = uT + (P) * 12;                                     \
            const ulonglong2 ua = *(const ulonglong2*)(ub_);                      \
            const ulonglong2 ubp = *(const ulonglong2*)(ub_ + 4);                 \
            const uint64_t  ucp = *(const uint64_t*)(ub_ + 8);                    \
            uint64_t up[5] = { ua.x, ua.y, ubp.x, ubp.y, ucp };                   \
            _Pragma("unroll")                                                     \
            for (int k5 = 0; k5 < 5; ++k5) {                                      \
                uint64_t t = fma2(up[k5], s2, o22);                               \
                uint64_t w = mul2(r2, up[k5]);                                    \
                q[k5] = fma2(q[k5], t, w);                                        \
            }                                                                     \
            float o1n = 3.0f * (o1 * o2);                                         \
            if (RENORM) {                                                         \
                uint64_t ss = add2(add2(q[0], q[1]),                              \
                                   add2(add2(q[2], q[3]), q[4]));                 \
                float slo, shi; unpk2(ss, slo, shi);                              \
                float csum = slo + shi + o1n;                                     \
                float inv = __fdividef(1.0f, csum);                               \
                uint64_t inv2 = pk2(inv, inv);                                    \
                _Pragma("unroll")                                                 \
                for (int k5 = 0; k5 < 5; ++k5) q[k5] = mul2(q[k5], inv2);         \
                o1n *= inv;                                                       \
            }                                                                     \
            o1 = o1n;                                                             \
        }

        DS_STEP(1, sv.y, false)
        DS_STEP(2, sv.z, false)
        DS_STEP(3, sv.w, false)
        #pragma unroll 1
        for (int g = 1; g < 32; ++g) {
            sv = srow[g];
            const int p0 = g * 4;
            DS_STEP(p0 + 0, sv.x, true)
            DS_STEP(p0 + 1, sv.y, false)
            DS_STEP(p0 + 2, sv.z, false)
            DS_STEP(p0 + 3, sv.w, false)
        }
        #undef DS_STEP

        {
            uint64_t ss = add2(add2(q[0], q[1]), add2(add2(q[2], q[3]), q[4]));
            float slo, shi; unpk2(ss, slo, shi);
            float tot = slo + shi + o1;
            float inv = 1.0f / tot;
            float* op = out + (size_t)(blockRow + r) * (C_DIM + 1);
            #pragma unroll
            for (int k5 = 0; k5 < 5; ++k5) {
                float a, b; unpk2(q[k5], a, b);
                op[k5 * 2]     = a * inv;
                op[k5 * 2 + 1] = b * inv;
            }
            op[C_DIM] = o1 * inv;
        }
    }
}

extern "C" void kernel_launch(void* const* d_in, const int* in_sizes, int n_in,
                              void* d_out, int out_size)
{
    const float* x    = (const float*)d_in[0];
    const float* w    = (const float*)d_in[1];
    const float* eta  = (const float*)d_in[2];
    const float* xi   = (const float*)d_in[3];
    const float* beta = (const float*)d_in[4];
    float* out = (float*)d_out;

    prep_kernel<<<128, 128>>>(w, eta, xi, beta);

    cudaFuncSetAttribute(ds_mma_kernel,
                         cudaFuncAttributeMaxDynamicSharedMemorySize, SMEM_ALLOC);
    ds_mma_kernel<<<B_TOTAL / MT, THREADS, SMEM_ALLOC>>>(x, out);
}